// round 2
// baseline (speedup 1.0000x reference)
#include <cuda_runtime.h>
#include <cuda_bf16.h>
#include <cstdint>

// Problem constants
#define B_  32
#define Q_  500
#define T_  128
#define NC_ 80
#define BQ_ (B_ * Q_)     // 16000
#define BT_ (B_ * T_)     // 4096

#define TILE 64

// Scratch (device globals: allocation-free rule)
__device__ float g_probT[NC_ * BQ_];   // TRANSPOSED softmax probs [cls][row], 5.12 MB
__device__ float g_row[BQ_ * 12];      // per-query: nx1,ny1,nx2,ny2, x1,y1,x2,y2, w,h,area, pad
__device__ float g_col[BT_ * 12];      // per-target: same layout
__device__ int   g_cls[BT_];           // target class ids

// ---------------------------------------------------------------------------
// Prep 1: softmax over logits rows + per-query box precompute.
// One warp per row, 8 rows per 256-thread block. Softmax staged in shared,
// then written TRANSPOSED to g_probT with 32B-segment coalescing.
// ---------------------------------------------------------------------------
__global__ void prep_rows_kernel(const float* __restrict__ logits,
                                 const float* __restrict__ boxes,
                                 const float* __restrict__ img_sz)
{
    __shared__ float s_p[8][84];   // pad 84: 84*r mod 32 = 20r -> conflict-free

    const int row0 = blockIdx.x * 8;
    const int wr   = threadIdx.x >> 5;     // warp -> local row
    const int lane = threadIdx.x & 31;
    const int row  = row0 + wr;

    const float* lg = logits + (size_t)row * NC_;
    float v0 = lg[lane];
    float v1 = lg[lane + 32];
    float v2 = (lane < 16) ? lg[lane + 64] : -3.4e38f;

    float m = fmaxf(v0, fmaxf(v1, v2));
    #pragma unroll
    for (int o = 16; o; o >>= 1) m = fmaxf(m, __shfl_xor_sync(0xffffffffu, m, o));

    float e0 = __expf(v0 - m);
    float e1 = __expf(v1 - m);
    float e2 = (lane < 16) ? __expf(v2 - m) : 0.f;
    float s = e0 + e1 + e2;
    #pragma unroll
    for (int o = 16; o; o >>= 1) s += __shfl_xor_sync(0xffffffffu, s, o);

    float inv = __fdividef(1.f, s);
    s_p[wr][lane]      = e0 * inv;
    s_p[wr][lane + 32] = e1 * inv;
    if (lane < 16) s_p[wr][lane + 64] = e2 * inv;

    if (lane == 0) {
        int b = row / Q_;
        const float* bx = boxes + (size_t)row * 4;
        float x1 = bx[0], y1 = bx[1], x2 = bx[2], y2 = bx[3];
        float s0 = img_sz[b * 4 + 0], s1 = img_sz[b * 4 + 1];
        float s2 = img_sz[b * 4 + 2], s3 = img_sz[b * 4 + 3];
        float w = x2 - x1, h = y2 - y1;
        float* r = g_row + row * 12;
        r[0] = __fdividef(x1, s0);
        r[1] = __fdividef(y1, s1);
        r[2] = __fdividef(x2, s2);
        r[3] = __fdividef(y2, s3);
        r[4] = x1; r[5] = y1; r[6] = x2; r[7] = y2;
        r[8] = w;  r[9] = h;  r[10] = w * h; r[11] = 0.f;
    }
    __syncthreads();

    // Transposed store: probT[cls][row0..row0+7]. Lanes cover 8 consecutive
    // rows per class -> 32B segments, 4 classes per warp-store.
    for (int idx = threadIdx.x; idx < NC_ * 8; idx += 256) {
        int cls = idx >> 3;
        int r   = idx & 7;
        g_probT[(size_t)cls * BQ_ + row0 + r] = s_p[r][cls];
    }
}

// ---------------------------------------------------------------------------
// Prep 2: per-target box precompute + class id.
// ---------------------------------------------------------------------------
__global__ void prep_cols_kernel(const float* __restrict__ tboxes,
                                 const int*   __restrict__ tlabels,
                                 const float* __restrict__ img_sz_tgt)
{
    int j = blockIdx.x * blockDim.x + threadIdx.x;
    if (j >= BT_) return;

    const float* bx = tboxes + (size_t)j * 4;
    const float* sz = img_sz_tgt + (size_t)j * 4;
    float x1 = bx[0], y1 = bx[1], x2 = bx[2], y2 = bx[3];
    float w = x2 - x1, h = y2 - y1;
    float* c = g_col + j * 12;
    c[0] = __fdividef(x1, sz[0]);
    c[1] = __fdividef(y1, sz[1]);
    c[2] = __fdividef(x2, sz[2]);
    c[3] = __fdividef(y2, sz[3]);
    c[4] = x1; c[5] = y1; c[6] = x2; c[7] = y2;
    c[8] = w;  c[9] = h;  c[10] = w * h; c[11] = 0.f;

    g_cls[j] = tlabels[j];
}

// ---------------------------------------------------------------------------
// Main: cost matrix [BQ, BT]. 64x64 block tile, 4 rows x 4 cols per thread.
// Class probs staged tile-wide in shared (coalesced fill from probT),
// eliminating the divergent per-element global gather.
// ---------------------------------------------------------------------------
__global__ __launch_bounds__(256, 2)
void cost_kernel(float* __restrict__ out)
{
    __shared__ float sr[TILE][13];      // row box data, stride 13 conflict-free
    __shared__ float sc[TILE][13];      // col box data
    __shared__ int   scls[TILE];        // col class ids
    __shared__ float spp[TILE][68];     // gathered probs [row][col], pad 68

    const int r0 = blockIdx.y * TILE;
    const int c0 = blockIdx.x * TILE;
    const int tid = threadIdx.x;

    if (tid < TILE) scls[tid] = g_cls[c0 + tid];
    for (int idx = tid; idx < TILE * 12; idx += 256) {
        int e = idx / 12, f = idx % 12;
        sr[e][f] = g_row[(r0 + e) * 12 + f];
        sc[e][f] = g_col[(c0 + e) * 12 + f];
    }
    __syncthreads();

    // Fill prob tile: warp lanes read 32 consecutive rows of one class column
    // -> one 128B wavefront per LDG (16 LDG/thread total).
    #pragma unroll
    for (int idx = tid; idx < TILE * TILE; idx += 256) {
        int col = idx >> 6;
        int row = idx & 63;
        spp[row][col] = g_probT[(size_t)scls[col] * BQ_ + r0 + row];
    }
    __syncthreads();

    const int tc = tid & 15;       // column group (4 consecutive cols)
    const int tr = tid >> 4;       // row group (4 rows)
    const int rloc = tr * 4;
    const int cloc = tc * 4;

    // Row data into registers
    float Rnx1[4], Rny1[4], Rnx2[4], Rny2[4];
    float Rx1[4], Ry1[4], Rx2[4], Ry2[4];
    float Rw[4], Rh[4], Ra[4];
    #pragma unroll
    for (int rr = 0; rr < 4; rr++) {
        Rnx1[rr] = sr[rloc + rr][0];
        Rny1[rr] = sr[rloc + rr][1];
        Rnx2[rr] = sr[rloc + rr][2];
        Rny2[rr] = sr[rloc + rr][3];
        Rx1[rr]  = sr[rloc + rr][4];
        Ry1[rr]  = sr[rloc + rr][5];
        Rx2[rr]  = sr[rloc + rr][6];
        Ry2[rr]  = sr[rloc + rr][7];
        Rw[rr]   = sr[rloc + rr][8];
        Rh[rr]   = sr[rloc + rr][9];
        Ra[rr]   = sr[rloc + rr][10];
    }

    float res[4][4];

    #pragma unroll
    for (int cc = 0; cc < 4; cc++) {
        const int c = cloc + cc;
        const float cnx1 = sc[c][0], cny1 = sc[c][1];
        const float cnx2 = sc[c][2], cny2 = sc[c][3];
        const float ctx1 = sc[c][4], cty1 = sc[c][5];
        const float ctx2 = sc[c][6], cty2 = sc[c][7];
        const float cwt  = sc[c][8], cht  = sc[c][9];
        const float cat  = sc[c][10];

        #pragma unroll
        for (int rr = 0; rr < 4; rr++) {
            // intersection extents (raw, before clamp)
            float m2x = fminf(Rx2[rr], ctx2);
            float M1x = fmaxf(Rx1[rr], ctx1);
            float m2y = fminf(Ry2[rr], cty2);
            float M1y = fmaxf(Ry1[rr], cty1);
            float wrx = m2x - M1x;
            float wry = m2y - M1y;
            float iw  = fmaxf(wrx, 0.f);
            float ih  = fmaxf(wry, 0.f);
            // enclosing extents via max = sum - min identity
            float ex = (Rw[rr] + cwt) - wrx;
            float ey = (Rh[rr] + cht) - wry;
            float inter = iw * ih;
            float areae = ex * ey;
            float uni   = (Ra[rr] + cat) - inter;
            // giou = inter/uni + uni/areae - 1  (single fast division)
            float num = fmaf(inter, areae, uni * uni);
            float den = uni * areae;

            // L1 of normalized boxes
            float cb = fabsf(Rnx1[rr] - cnx1) + fabsf(Rny1[rr] - cny1)
                     + fabsf(Rnx2[rr] - cnx2) + fabsf(Rny2[rr] - cny2);

            // class prob from shared tile
            float p = spp[rloc + rr][c];

            // C = 5*cb - 2*p + 2 - 2*(num/den)
            float base = fmaf(5.f, cb, fmaf(-2.f, p, 2.f));
            res[rr][cc] = fmaf(-2.f, __fdividef(num, den), base);
        }
    }

    // Coalesced float4 stores
    #pragma unroll
    for (int rr = 0; rr < 4; rr++) {
        size_t i = (size_t)(r0 + rloc + rr);
        float4 v = make_float4(res[rr][0], res[rr][1], res[rr][2], res[rr][3]);
        *reinterpret_cast<float4*>(out + i * BT_ + c0 + cloc) = v;
    }
}

// ---------------------------------------------------------------------------
extern "C" void kernel_launch(void* const* d_in, const int* in_sizes, int n_in,
                              void* d_out, int out_size)
{
    const float* pred_logits  = (const float*)d_in[0];   // [B,Q,NC]
    const float* pred_boxes   = (const float*)d_in[1];   // [B,Q,4]
    const int*   tgt_labels   = (const int*)d_in[2];     // [B,T]
    const float* tgt_boxes    = (const float*)d_in[3];   // [B,T,4]
    const float* img_sz       = (const float*)d_in[4];   // [B,4]
    const float* img_sz_tgt   = (const float*)d_in[5];   // [B,T,4]
    float* out = (float*)d_out;

    prep_rows_kernel<<<BQ_ / 8, 256>>>(pred_logits, pred_boxes, img_sz);
    prep_cols_kernel<<<(BT_ + 255) / 256, 256>>>(tgt_boxes, tgt_labels, img_sz_tgt);

    dim3 grid(BT_ / TILE, BQ_ / TILE);   // (64, 250)
    cost_kernel<<<grid, 256>>>(out);
}

// round 3
// speedup vs baseline: 1.4847x; 1.4847x over previous
#include <cuda_runtime.h>
#include <cuda_bf16.h>
#include <cstdint>

// Problem constants
#define B_  32
#define Q_  500
#define T_  128
#define NC_ 80
#define BQ_ (B_ * Q_)     // 16000
#define BT_ (B_ * T_)     // 4096

#define TILE 64
#define PSTRIDE 65        // odd stride -> conflict-free class-indexed LDS

// Scratch (device globals: allocation-free rule)
__device__ float g_probT[NC_ * BQ_];   // TRANSPOSED softmax probs [cls][row], 5.12 MB
__device__ float g_row[BQ_ * 12];      // per-query: nx1,ny1,nx2,ny2, x1,y1,x2,y2, w,h,area, pad
__device__ float g_col[BT_ * 12];      // per-target: same layout
__device__ int   g_cls[BT_];           // target class ids

// ---------------------------------------------------------------------------
// Prep 1: softmax over logits rows + per-query box precompute.
// One warp per row, 8 rows per 256-thread block. Softmax staged in shared,
// then written TRANSPOSED to g_probT.
// ---------------------------------------------------------------------------
__global__ void prep_rows_kernel(const float* __restrict__ logits,
                                 const float* __restrict__ boxes,
                                 const float* __restrict__ img_sz)
{
    __shared__ float s_p[8][84];   // pad 84 -> conflict-free transpose read

    const int row0 = blockIdx.x * 8;
    const int wr   = threadIdx.x >> 5;     // warp -> local row
    const int lane = threadIdx.x & 31;
    const int row  = row0 + wr;

    const float* lg = logits + (size_t)row * NC_;
    float v0 = lg[lane];
    float v1 = lg[lane + 32];
    float v2 = (lane < 16) ? lg[lane + 64] : -3.4e38f;

    float m = fmaxf(v0, fmaxf(v1, v2));
    #pragma unroll
    for (int o = 16; o; o >>= 1) m = fmaxf(m, __shfl_xor_sync(0xffffffffu, m, o));

    float e0 = __expf(v0 - m);
    float e1 = __expf(v1 - m);
    float e2 = (lane < 16) ? __expf(v2 - m) : 0.f;
    float s = e0 + e1 + e2;
    #pragma unroll
    for (int o = 16; o; o >>= 1) s += __shfl_xor_sync(0xffffffffu, s, o);

    float inv = __fdividef(1.f, s);
    s_p[wr][lane]      = e0 * inv;
    s_p[wr][lane + 32] = e1 * inv;
    if (lane < 16) s_p[wr][lane + 64] = e2 * inv;

    if (lane == 0) {
        int b = row / Q_;
        const float* bx = boxes + (size_t)row * 4;
        float x1 = bx[0], y1 = bx[1], x2 = bx[2], y2 = bx[3];
        float s0 = img_sz[b * 4 + 0], s1 = img_sz[b * 4 + 1];
        float s2 = img_sz[b * 4 + 2], s3 = img_sz[b * 4 + 3];
        float w = x2 - x1, h = y2 - y1;
        float* r = g_row + row * 12;
        r[0] = __fdividef(x1, s0);
        r[1] = __fdividef(y1, s1);
        r[2] = __fdividef(x2, s2);
        r[3] = __fdividef(y2, s3);
        r[4] = x1; r[5] = y1; r[6] = x2; r[7] = y2;
        r[8] = w;  r[9] = h;  r[10] = w * h; r[11] = 0.f;
    }
    __syncthreads();

    // Transposed store: probT[cls][row0..row0+7].
    for (int idx = threadIdx.x; idx < NC_ * 8; idx += 256) {
        int cls = idx >> 3;
        int r   = idx & 7;
        g_probT[(size_t)cls * BQ_ + row0 + r] = s_p[r][cls];
    }
}

// ---------------------------------------------------------------------------
// Prep 2: per-target box precompute + class id.
// ---------------------------------------------------------------------------
__global__ void prep_cols_kernel(const float* __restrict__ tboxes,
                                 const int*   __restrict__ tlabels,
                                 const float* __restrict__ img_sz_tgt)
{
    int j = blockIdx.x * blockDim.x + threadIdx.x;
    if (j >= BT_) return;

    const float* bx = tboxes + (size_t)j * 4;
    const float* sz = img_sz_tgt + (size_t)j * 4;
    float x1 = bx[0], y1 = bx[1], x2 = bx[2], y2 = bx[3];
    float w = x2 - x1, h = y2 - y1;
    float* c = g_col + j * 12;
    c[0] = __fdividef(x1, sz[0]);
    c[1] = __fdividef(y1, sz[1]);
    c[2] = __fdividef(x2, sz[2]);
    c[3] = __fdividef(y2, sz[3]);
    c[4] = x1; c[5] = y1; c[6] = x2; c[7] = y2;
    c[8] = w;  c[9] = h;  c[10] = w * h; c[11] = 0.f;

    g_cls[j] = tlabels[j];
}

// ---------------------------------------------------------------------------
// Main: cost matrix [BQ, BT]. 64x64 tile, 4 rows x 4 cols per thread.
// ALL 80 classes of the 64-row band staged in shared with stride 65:
//   - fill: coalesced LDG (128B/warp), stride-1 STS -> zero bank conflicts
//   - read: sprob[cls*65 + row], distinct cls per lane -> bank = cls+row,
//     near-conflict-free; same class = broadcast.
// ---------------------------------------------------------------------------
__global__ __launch_bounds__(256, 3)
void cost_kernel(float* __restrict__ out)
{
    __shared__ float sr[TILE][13];          // row box data
    __shared__ float sc[TILE][13];          // col box data
    __shared__ int   scls[TILE];            // col class ids
    __shared__ float sprob[NC_ * PSTRIDE];  // [cls][row] for this row band, 20.8 KB

    const int r0 = blockIdx.y * TILE;
    const int c0 = blockIdx.x * TILE;
    const int tid = threadIdx.x;

    if (tid < TILE) scls[tid] = g_cls[c0 + tid];
    for (int idx = tid; idx < TILE * 12; idx += 256) {
        int e = idx / 12, f = idx % 12;
        sr[e][f] = g_row[(r0 + e) * 12 + f];
        sc[e][f] = g_col[(c0 + e) * 12 + f];
    }
    // Fill prob band: 80 classes x 64 rows, coalesced reads, stride-1 writes.
    #pragma unroll 4
    for (int idx = tid; idx < NC_ * TILE; idx += 256) {
        int cls = idx >> 6;          // 0..79
        int row = idx & 63;          // 0..63
        sprob[cls * PSTRIDE + row] = g_probT[(size_t)cls * BQ_ + r0 + row];
    }
    __syncthreads();

    const int tc = tid & 15;       // column group (4 consecutive cols)
    const int tr = tid >> 4;       // row group (4 rows)
    const int rloc = tr * 4;
    const int cloc = tc * 4;

    // Row data into registers
    float Rnx1[4], Rny1[4], Rnx2[4], Rny2[4];
    float Rx1[4], Ry1[4], Rx2[4], Ry2[4];
    float Rw[4], Rh[4], Ra[4];
    #pragma unroll
    for (int rr = 0; rr < 4; rr++) {
        Rnx1[rr] = sr[rloc + rr][0];
        Rny1[rr] = sr[rloc + rr][1];
        Rnx2[rr] = sr[rloc + rr][2];
        Rny2[rr] = sr[rloc + rr][3];
        Rx1[rr]  = sr[rloc + rr][4];
        Ry1[rr]  = sr[rloc + rr][5];
        Rx2[rr]  = sr[rloc + rr][6];
        Ry2[rr]  = sr[rloc + rr][7];
        Rw[rr]   = sr[rloc + rr][8];
        Rh[rr]   = sr[rloc + rr][9];
        Ra[rr]   = sr[rloc + rr][10];
    }

    // Per-thread column class bases (register-resident, no gather dependency)
    int pbase[4];
    #pragma unroll
    for (int cc = 0; cc < 4; cc++)
        pbase[cc] = scls[cloc + cc] * PSTRIDE + rloc;

    float res[4][4];

    #pragma unroll
    for (int cc = 0; cc < 4; cc++) {
        const int c = cloc + cc;
        const float cnx1 = sc[c][0], cny1 = sc[c][1];
        const float cnx2 = sc[c][2], cny2 = sc[c][3];
        const float ctx1 = sc[c][4], cty1 = sc[c][5];
        const float ctx2 = sc[c][6], cty2 = sc[c][7];
        const float cwt  = sc[c][8], cht  = sc[c][9];
        const float cat  = sc[c][10];

        #pragma unroll
        for (int rr = 0; rr < 4; rr++) {
            // intersection extents (raw, before clamp)
            float m2x = fminf(Rx2[rr], ctx2);
            float M1x = fmaxf(Rx1[rr], ctx1);
            float m2y = fminf(Ry2[rr], cty2);
            float M1y = fmaxf(Ry1[rr], cty1);
            float wrx = m2x - M1x;
            float wry = m2y - M1y;
            float iw  = fmaxf(wrx, 0.f);
            float ih  = fmaxf(wry, 0.f);
            // enclosing extents via max = sum - min identity
            float ex = (Rw[rr] + cwt) - wrx;
            float ey = (Rh[rr] + cht) - wry;
            float inter = iw * ih;
            float areae = ex * ey;
            float uni   = (Ra[rr] + cat) - inter;
            // giou = inter/uni + uni/areae - 1  (single fast division)
            float num = fmaf(inter, areae, uni * uni);
            float den = uni * areae;

            // L1 of normalized boxes
            float cb = fabsf(Rnx1[rr] - cnx1) + fabsf(Rny1[rr] - cny1)
                     + fabsf(Rnx2[rr] - cnx2) + fabsf(Rny2[rr] - cny2);

            // class prob: conflict-free shared read
            float p = sprob[pbase[cc] + rr];

            // C = 5*cb - 2*p + 2 - 2*(num/den)
            float base = fmaf(5.f, cb, fmaf(-2.f, p, 2.f));
            res[rr][cc] = fmaf(-2.f, __fdividef(num, den), base);
        }
    }

    // Coalesced float4 stores
    #pragma unroll
    for (int rr = 0; rr < 4; rr++) {
        size_t i = (size_t)(r0 + rloc + rr);
        float4 v = make_float4(res[rr][0], res[rr][1], res[rr][2], res[rr][3]);
        *reinterpret_cast<float4*>(out + i * BT_ + c0 + cloc) = v;
    }
}

// ---------------------------------------------------------------------------
extern "C" void kernel_launch(void* const* d_in, const int* in_sizes, int n_in,
                              void* d_out, int out_size)
{
    const float* pred_logits  = (const float*)d_in[0];   // [B,Q,NC]
    const float* pred_boxes   = (const float*)d_in[1];   // [B,Q,4]
    const int*   tgt_labels   = (const int*)d_in[2];     // [B,T]
    const float* tgt_boxes    = (const float*)d_in[3];   // [B,T,4]
    const float* img_sz       = (const float*)d_in[4];   // [B,4]
    const float* img_sz_tgt   = (const float*)d_in[5];   // [B,T,4]
    float* out = (float*)d_out;

    prep_rows_kernel<<<BQ_ / 8, 256>>>(pred_logits, pred_boxes, img_sz);
    prep_cols_kernel<<<(BT_ + 255) / 256, 256>>>(tgt_boxes, tgt_labels, img_sz_tgt);

    dim3 grid(BT_ / TILE, BQ_ / TILE);   // (64, 250)
    cost_kernel<<<grid, 256>>>(out);
}

// round 4
// speedup vs baseline: 2.0073x; 1.3520x over previous
#include <cuda_runtime.h>
#include <cuda_bf16.h>
#include <cstdint>

// Problem constants
#define B_  32
#define Q_  500
#define T_  128
#define NC_ 80
#define BQ_ (B_ * Q_)     // 16000
#define BT_ (B_ * T_)     // 4096

#define TR 32             // tile rows
#define TC 128            // tile cols

// Scratch (device globals: allocation-free rule)
__device__ float g_prob[BQ_ * NC_];    // pv = 2 - 2*softmax, [row][cls]
__device__ float g_row[BQ_ * 12];      // per-query: 5*nx1,5*ny1,5*nx2,5*ny2, x1,y1,x2,y2, w,h,area, pad
__device__ float g_col[BT_ * 12];      // per-target: same layout
__device__ int   g_cls[BT_];           // target class ids

// ---------------------------------------------------------------------------
// Prep 1: softmax (stored as pv = 2 - 2*p) + per-query box precompute.
// One warp per row, 8 rows per 256-thread block.
// ---------------------------------------------------------------------------
__global__ void prep_rows_kernel(const float* __restrict__ logits,
                                 const float* __restrict__ boxes,
                                 const float* __restrict__ img_sz)
{
    int row  = blockIdx.x * 8 + (threadIdx.x >> 5);
    int lane = threadIdx.x & 31;

    const float* lg = logits + (size_t)row * NC_;
    float v0 = lg[lane];
    float v1 = lg[lane + 32];
    float v2 = (lane < 16) ? lg[lane + 64] : -3.4e38f;

    float m = fmaxf(v0, fmaxf(v1, v2));
    #pragma unroll
    for (int o = 16; o; o >>= 1) m = fmaxf(m, __shfl_xor_sync(0xffffffffu, m, o));

    float e0 = __expf(v0 - m);
    float e1 = __expf(v1 - m);
    float e2 = (lane < 16) ? __expf(v2 - m) : 0.f;
    float s = e0 + e1 + e2;
    #pragma unroll
    for (int o = 16; o; o >>= 1) s += __shfl_xor_sync(0xffffffffu, s, o);

    // pv = 2 - 2*p  (class cost + giou "+2" constant pre-folded)
    float ninv2 = __fdividef(-2.f, s);
    float* pr = g_prob + (size_t)row * NC_;
    pr[lane]      = fmaf(e0, ninv2, 2.f);
    pr[lane + 32] = fmaf(e1, ninv2, 2.f);
    if (lane < 16) pr[lane + 64] = fmaf(e2, ninv2, 2.f);

    if (lane == 0) {
        int b = row / Q_;
        const float* bx = boxes + (size_t)row * 4;
        float x1 = bx[0], y1 = bx[1], x2 = bx[2], y2 = bx[3];
        float s0 = img_sz[b * 4 + 0], s1 = img_sz[b * 4 + 1];
        float s2 = img_sz[b * 4 + 2], s3 = img_sz[b * 4 + 3];
        float w = x2 - x1, h = y2 - y1;
        float* r = g_row + row * 12;
        // normalized coords pre-scaled by COST_BBOX=5
        r[0] = __fdividef(5.f * x1, s0);
        r[1] = __fdividef(5.f * y1, s1);
        r[2] = __fdividef(5.f * x2, s2);
        r[3] = __fdividef(5.f * y2, s3);
        r[4] = x1; r[5] = y1; r[6] = x2; r[7] = y2;
        r[8] = w;  r[9] = h;  r[10] = w * h; r[11] = 0.f;
    }
}

// ---------------------------------------------------------------------------
// Prep 2: per-target box precompute (normalized pre-scaled by 5) + class id.
// ---------------------------------------------------------------------------
__global__ void prep_cols_kernel(const float* __restrict__ tboxes,
                                 const int*   __restrict__ tlabels,
                                 const float* __restrict__ img_sz_tgt)
{
    int j = blockIdx.x * blockDim.x + threadIdx.x;
    if (j >= BT_) return;

    const float* bx = tboxes + (size_t)j * 4;
    const float* sz = img_sz_tgt + (size_t)j * 4;
    float x1 = bx[0], y1 = bx[1], x2 = bx[2], y2 = bx[3];
    float w = x2 - x1, h = y2 - y1;
    float* c = g_col + j * 12;
    c[0] = __fdividef(5.f * x1, sz[0]);
    c[1] = __fdividef(5.f * y1, sz[1]);
    c[2] = __fdividef(5.f * x2, sz[2]);
    c[3] = __fdividef(5.f * y2, sz[3]);
    c[4] = x1; c[5] = y1; c[6] = x2; c[7] = y2;
    c[8] = w;  c[9] = h;  c[10] = w * h; c[11] = 0.f;

    g_cls[j] = tlabels[j];
}

// ---------------------------------------------------------------------------
// Main: cost matrix [BQ, BT]. 32x128 tile, thread = 4 rows x 4 cols.
// Warp = one 4-row group x full 128-col width:
//   - gather LDG: all lanes on ONE prob row (320B) -> <=3-4 L1 wavefronts
//   - stores: warp-wide 512B contiguous STG.128
// ---------------------------------------------------------------------------
__global__ __launch_bounds__(256, 3)
void cost_kernel(float* __restrict__ out)
{
    __shared__ float sr[TR][13];        // row box data (broadcast reads)
    __shared__ float sc[TC][13];        // col box data (stride 13: conflict-free)
    __shared__ int   scls[TC];          // col class ids

    const int r0 = blockIdx.y * TR;
    const int c0 = blockIdx.x * TC;
    const int tid = threadIdx.x;

    for (int idx = tid; idx < TC; idx += 256) scls[idx] = g_cls[c0 + idx];
    for (int idx = tid; idx < TR * 12; idx += 256) {
        int e = idx / 12, f = idx % 12;
        sr[e][f] = g_row[(r0 + e) * 12 + f];
    }
    for (int idx = tid; idx < TC * 12; idx += 256) {
        int e = idx / 12, f = idx % 12;
        sc[e][f] = g_col[(c0 + e) * 12 + f];
    }
    __syncthreads();

    const int tc = tid & 31;       // column group (4 consecutive cols)
    const int tr = tid >> 5;       // row group (4 rows); constant per warp
    const int rloc = tr * 4;
    const int cloc = tc * 4;

    // Row data into registers
    float Rnx1[4], Rny1[4], Rnx2[4], Rny2[4];
    float Rx1[4], Ry1[4], Rx2[4], Ry2[4];
    float Rw[4], Rh[4], Ra[4];
    #pragma unroll
    for (int rr = 0; rr < 4; rr++) {
        Rnx1[rr] = sr[rloc + rr][0];
        Rny1[rr] = sr[rloc + rr][1];
        Rnx2[rr] = sr[rloc + rr][2];
        Rny2[rr] = sr[rloc + rr][3];
        Rx1[rr]  = sr[rloc + rr][4];
        Ry1[rr]  = sr[rloc + rr][5];
        Rx2[rr]  = sr[rloc + rr][6];
        Ry2[rr]  = sr[rloc + rr][7];
        Rw[rr]   = sr[rloc + rr][8];
        Rh[rr]   = sr[rloc + rr][9];
        Ra[rr]   = sr[rloc + rr][10];
    }

    // Per-thread class ids for the 4 columns
    int clsr[4];
    #pragma unroll
    for (int cc = 0; cc < 4; cc++) clsr[cc] = scls[cloc + cc];

    const float* prow = g_prob + (size_t)(r0 + rloc) * NC_;

    float res[4][4];

    #pragma unroll
    for (int cc = 0; cc < 4; cc++) {
        const int c = cloc + cc;
        const float cnx1 = sc[c][0], cny1 = sc[c][1];
        const float cnx2 = sc[c][2], cny2 = sc[c][3];
        const float ctx1 = sc[c][4], cty1 = sc[c][5];
        const float ctx2 = sc[c][6], cty2 = sc[c][7];
        const float cwt  = sc[c][8], cht  = sc[c][9];
        const float cat  = sc[c][10];
        const int   cls  = clsr[cc];

        #pragma unroll
        for (int rr = 0; rr < 4; rr++) {
            // intersection extents (raw, before clamp)
            float m2x = fminf(Rx2[rr], ctx2);
            float M1x = fmaxf(Rx1[rr], ctx1);
            float m2y = fminf(Ry2[rr], cty2);
            float M1y = fmaxf(Ry1[rr], cty1);
            float wrx = m2x - M1x;
            float wry = m2y - M1y;
            float iw  = fmaxf(wrx, 0.f);
            float ih  = fmaxf(wry, 0.f);
            // enclosing extents via max = sum - min identity
            float ex = (Rw[rr] + cwt) - wrx;
            float ey = (Rh[rr] + cht) - wry;
            float inter = iw * ih;
            float areae = ex * ey;
            float uni   = (Ra[rr] + cat) - inter;
            // giou terms with single fast division
            float num = fmaf(inter, areae, uni * uni);
            float den = uni * areae;

            // 5*L1 of normalized boxes (coords pre-scaled by 5)
            float cb = (fabsf(Rnx1[rr] - cnx1) + fabsf(Rny1[rr] - cny1))
                     + (fabsf(Rnx2[rr] - cnx2) + fabsf(Rny2[rr] - cny2));

            // pv = 2 - 2*p  (one LDG, all lanes on the same prob row)
            float pv = __ldg(&prow[rr * NC_ + cls]);

            // C = cb + pv - 2*(num/den)
            float base = cb + pv;
            res[rr][cc] = fmaf(-2.f, __fdividef(num, den), base);
        }
    }

    // Coalesced float4 stores (warp covers 512B contiguous per rr)
    #pragma unroll
    for (int rr = 0; rr < 4; rr++) {
        size_t i = (size_t)(r0 + rloc + rr);
        float4 v = make_float4(res[rr][0], res[rr][1], res[rr][2], res[rr][3]);
        *reinterpret_cast<float4*>(out + i * BT_ + c0 + cloc) = v;
    }
}

// ---------------------------------------------------------------------------
extern "C" void kernel_launch(void* const* d_in, const int* in_sizes, int n_in,
                              void* d_out, int out_size)
{
    const float* pred_logits  = (const float*)d_in[0];   // [B,Q,NC]
    const float* pred_boxes   = (const float*)d_in[1];   // [B,Q,4]
    const int*   tgt_labels   = (const int*)d_in[2];     // [B,T]
    const float* tgt_boxes    = (const float*)d_in[3];   // [B,T,4]
    const float* img_sz       = (const float*)d_in[4];   // [B,4]
    const float* img_sz_tgt   = (const float*)d_in[5];   // [B,T,4]
    float* out = (float*)d_out;

    prep_rows_kernel<<<BQ_ / 8, 256>>>(pred_logits, pred_boxes, img_sz);
    prep_cols_kernel<<<(BT_ + 255) / 256, 256>>>(tgt_boxes, tgt_labels, img_sz_tgt);

    dim3 grid(BT_ / TC, BQ_ / TR);   // (32, 500)
    cost_kernel<<<grid, 256>>>(out);
}